// round 14
// baseline (speedup 1.0000x reference)
#include <cuda_runtime.h>
#include <math.h>
#include <stdint.h>

#define Bq   32
#define Hc   384
#define Tn   1024
#define MAXL 4096
#define NBLK 512               // T/2 winograd blocks per batch
#define NTOT (Bq * NBLK)       // 16384 GEMM columns (m-dim)
#define KT   48                // 384/8 k-chunks
#define MT   (NTOT / 16)       // 1024 m-tiles
#define NT   48                // 384/8 n-tiles (ho)

// ---------------- scratch ----------------
__device__ float g_buf1[(size_t)Bq * Hc * Tn];
__device__ float g_M[4][Hc][NTOT];                       // phase GEMM outputs
__device__ float g_Vf[(size_t)4 * 2 * KT * MT * 128];    // A frags [p][h][kt][mt][lane][4]
__device__ float g_Bf[2][4 * 2 * KT * NT * 64];          // B frags [conv][p][h][kt][nt][lane][2]
__device__ float g_mean[Bq * Tn];
__device__ float g_rstd[Bq * Tn];
__device__ int   g_dur[Bq * Tn];
__device__ int   g_cum[Bq * Tn];

__device__ __forceinline__ uint32_t f2tf32(float x)
{
    uint32_t r;
    asm("cvt.rna.tf32.f32 %0, %1;" : "=r"(r) : "f"(x));
    return r;
}
__device__ __forceinline__ void tf32_split(float x, float& h, float& l)
{
    uint32_t hb = f2tf32(x);
    h = __uint_as_float(hb);
    l = __uint_as_float(f2tf32(x - h));
}

#define MMA_TF32(c, a, b) \
    asm volatile("mma.sync.aligned.m16n8k8.row.col.f32.tf32.tf32.f32 " \
        "{%0,%1,%2,%3}, {%4,%5,%6,%7}, {%8,%9}, {%0,%1,%2,%3};" \
        : "+f"((c)[0]), "+f"((c)[1]), "+f"((c)[2]), "+f"((c)[3]) \
        : "r"(__float_as_uint((a).x)), "r"(__float_as_uint((a).y)), \
          "r"(__float_as_uint((a).z)), "r"(__float_as_uint((a).w)), \
          "r"(__float_as_uint((b).x)), "r"(__float_as_uint((b).y)))

// ---------------- V prep: X -> A fragments (split hi/lo); optional fused LN+relu --
__global__ void vprep(const float* __restrict__ X, float* __restrict__ Af,
                      int useLN, const float* __restrict__ gam,
                      const float* __restrict__ bet)
{
    int gw = blockIdx.x * 8 + (threadIdx.x >> 5);   // warp per (kt, mt)
    int lane = threadIdx.x & 31;
    int kt = gw >> 10;
    int mt = gw & 1023;
    int g = lane >> 2, t4 = lane & 3;

    float4 outv[4][2];
#pragma unroll
    for (int s = 0; s < 4; s++) {
        int r  = g + ((s & 1) ? 8 : 0);
        int kk = t4 + ((s & 2) ? 4 : 0);
        int m = mt * 16 + r;
        int b = m >> 9, nb = m & 511;
        int hi = kt * 8 + kk;
        const float* xp = X + ((size_t)b * Hc + hi) * Tn;
        int t2 = 2 * nb;
        float gv = 1.f, bv = 0.f;
        float mn1 = 0.f, rs1 = 1.f, mn2 = 0.f, rs2 = 1.f;
        if (useLN) {
            gv = __ldg(gam + hi); bv = __ldg(bet + hi);
            mn1 = g_mean[b * Tn + t2];     rs1 = g_rstd[b * Tn + t2];
            mn2 = g_mean[b * Tn + t2 + 1]; rs2 = g_rstd[b * Tn + t2 + 1];
        }
        // aligned float2 covers d1, d2; only p0/p3 need odd neighbors
        float2 dc = *(const float2*)(xp + t2);
        float d1 = dc.x, d2 = dc.y;
        float d0 = (t2 > 0) ? __ldg(xp + t2 - 1) : 0.f;
        float d3 = (t2 + 2 < Tn) ? __ldg(xp + t2 + 2) : 0.f;
        if (useLN) {
            d1 = fmaxf((d1 - mn1) * rs1 * gv + bv, 0.f);
            d2 = fmaxf((d2 - mn2) * rs2 * gv + bv, 0.f);
            if (t2 > 0) {
                d0 = fmaxf((d0 - g_mean[b * Tn + t2 - 1]) * g_rstd[b * Tn + t2 - 1] * gv + bv, 0.f);
            }
            if (t2 + 2 < Tn) {
                d3 = fmaxf((d3 - g_mean[b * Tn + t2 + 2]) * g_rstd[b * Tn + t2 + 2] * gv + bv, 0.f);
            }
        }
        float v[4] = {d0 - d2, d1 + d2, d2 - d1, d1 - d3};
#pragma unroll
        for (int p = 0; p < 4; p++) {
            float h, l;
            tf32_split(v[p], h, l);
            ((float*)&outv[p][0])[s] = h;
            ((float*)&outv[p][1])[s] = l;
        }
    }
#pragma unroll
    for (int p = 0; p < 4; p++)
#pragma unroll
        for (int h = 0; h < 2; h++)
            *(float4*)(Af + ((((size_t)(p * 2 + h) * KT + kt) * MT + mt) * 128) + lane * 4)
                = outv[p][h];
}

// ---------------- B prep (both convs in one launch): W -> U_p fragments -----------
__global__ void bprep2(const float* __restrict__ W1, const float* __restrict__ W2,
                       float* __restrict__ BfAll)
{
    int conv = blockIdx.y;
    const float* W = conv ? W2 : W1;
    float* Bf = BfAll + (size_t)conv * 4 * 2 * KT * NT * 64;

    int gw = blockIdx.x * 8 + (threadIdx.x >> 5);
    int lane = threadIdx.x & 31;
    int kt = gw / NT, nt = gw % NT;
    int g = lane >> 2, t4 = lane & 3;
    int ho = nt * 8 + g;

    float2 outv[4][2];
#pragma unroll
    for (int s = 0; s < 2; s++) {
        int hi = kt * 8 + t4 + s * 4;
        const float* wp = W + ((size_t)ho * Hc + hi) * 3;
        float g0 = __ldg(wp), g1 = __ldg(wp + 1), g2 = __ldg(wp + 2);
        float u[4] = {g0, 0.5f * (g0 + g1 + g2), 0.5f * (g0 - g1 + g2), g2};
#pragma unroll
        for (int p = 0; p < 4; p++) {
            float h, l;
            tf32_split(u[p], h, l);
            ((float*)&outv[p][0])[s] = h;
            ((float*)&outv[p][1])[s] = l;
        }
    }
#pragma unroll
    for (int p = 0; p < 4; p++)
#pragma unroll
        for (int h = 0; h < 2; h++)
            *(float2*)(Bf + ((((size_t)(p * 2 + h) * KT + kt) * NT + nt) * 64) + lane * 2)
                = outv[p][h];
}

// ---------------- phase GEMM: 32m x 32n warp tile, 2 CTAs/SM, A depth-2 -----------
__global__ __launch_bounds__(256, 2)
void wino_mma(const float* __restrict__ Af, const float* __restrict__ Bf,
              float* __restrict__ M)
{
    const int p = blockIdx.z, mc = blockIdx.x, nc = blockIdx.y;
    const int w = threadIdx.x >> 5, lane = threadIdx.x & 31;
    const int wm = w & 3, wn = w >> 2;
    const int mt0 = mc * 8 + wm * 2;
    const int nt0 = nc * 8 + wn * 4;

    float c[8][4];
#pragma unroll
    for (int i = 0; i < 8; i++)
#pragma unroll
        for (int r = 0; r < 4; r++) c[i][r] = 0.f;

    const float* A0 = Af + (size_t)(p * 2 + 0) * KT * MT * 128 + (size_t)mt0 * 128 + lane * 4;
    const float* A1 = Af + (size_t)(p * 2 + 1) * KT * MT * 128 + (size_t)mt0 * 128 + lane * 4;
    const float* B0 = Bf + (size_t)(p * 2 + 0) * KT * NT * 64 + (size_t)nt0 * 64 + lane * 2;
    const float* B1 = Bf + (size_t)(p * 2 + 1) * KT * NT * 64 + (size_t)nt0 * 64 + lane * 2;

    float4 a[3][2][2];   // [buf][tile][half] — DRAM operand, depth-2 prefetch
    float2 b[2][4][2];   // [buf][tile][half] — L2 operand, depth-1

    auto loadA = [&](int kt, int bi) {
        const size_t ao = (size_t)kt * MT * 128;
#pragma unroll
        for (int i = 0; i < 2; i++) {
            a[bi][i][0] = __ldg((const float4*)(A0 + ao + (size_t)i * 128));
            a[bi][i][1] = __ldg((const float4*)(A1 + ao + (size_t)i * 128));
        }
    };
    auto loadB = [&](int kt, int bi) {
        const size_t bo = (size_t)kt * NT * 64;
#pragma unroll
        for (int j = 0; j < 4; j++) {
            b[bi][j][0] = __ldg((const float2*)(B0 + bo + (size_t)j * 64));
            b[bi][j][1] = __ldg((const float2*)(B1 + bo + (size_t)j * 64));
        }
    };

    loadA(0, 0);
    loadA(1, 1);
    loadB(0, 0);
#pragma unroll 3
    for (int kt = 0; kt < KT; kt++) {
        const int ca = kt % 3;
        const int cb = kt & 1;
        if (kt + 2 < KT) loadA(kt + 2, (kt + 2) % 3);
        if (kt + 1 < KT) loadB(kt + 1, cb ^ 1);
#pragma unroll
        for (int i = 0; i < 2; i++)
#pragma unroll
            for (int j = 0; j < 4; j++) {
                MMA_TF32(c[i * 4 + j], a[ca][i][0], b[cb][j][0]);
                MMA_TF32(c[i * 4 + j], a[ca][i][0], b[cb][j][1]);
                MMA_TF32(c[i * 4 + j], a[ca][i][1], b[cb][j][0]);
            }
    }

    const int g = lane >> 2, t4 = lane & 3;
#pragma unroll
    for (int i = 0; i < 2; i++)
#pragma unroll
        for (int j = 0; j < 4; j++) {
            int m  = mc * 128 + wm * 32 + i * 16 + g;
            int ho = nc * 64 + wn * 32 + j * 8 + 2 * t4;
            float* mp = M + ((size_t)p * Hc + ho) * NTOT + m;
            mp[0]        = c[i * 4 + j][0];
            mp[NTOT]     = c[i * 4 + j][1];
            mp[8]        = c[i * 4 + j][2];
            mp[NTOT + 8] = c[i * 4 + j][3];
        }
}

// ---------------- conv1 epilogue: output transform + LN stats ----------
__global__ __launch_bounds__(256, 4)
void wino_out_stats(const float* __restrict__ M, const float* __restrict__ bias,
                    float* __restrict__ Y)
{
    __shared__ float red[8][4][32];
    const int tid = threadIdx.x;
    const int cl = tid & 31;
    const int hgrp = tid >> 5;                 // 0..7
    const int col = blockIdx.x * 32 + cl;      // 0..16383
    const int b = col >> 9, nb = col & 511;
    const float* mp = M + col;
    const size_t PH = (size_t)Hc * NTOT;
    float* yb = Y + (size_t)b * Hc * Tn + 2 * nb;

    float s0 = 0.f, q0 = 0.f, s1 = 0.f, q1 = 0.f;
    const int h0 = hgrp * 48;
#pragma unroll 4
    for (int ho = h0; ho < h0 + 48; ho++) {
        size_t off = (size_t)ho * NTOT;
        float m1 = __ldg(mp + off);
        float m2 = __ldg(mp + off + PH);
        float m3 = __ldg(mp + off + 2 * PH);
        float m4 = __ldg(mp + off + 3 * PH);
        float bi = __ldg(bias + ho);
        float y0 = m1 + m2 + m3 + bi;
        float y1 = m2 - m3 - m4 + bi;
        *(float2*)(yb + (size_t)ho * Tn) = make_float2(y0, y1);
        s0 += y0; q0 += y0 * y0;
        s1 += y1; q1 += y1 * y1;
    }
    red[hgrp][0][cl] = s0;
    red[hgrp][1][cl] = q0;
    red[hgrp][2][cl] = s1;
    red[hgrp][3][cl] = q1;
    __syncthreads();
    if (hgrp == 0) {
        float S0 = 0.f, Q0 = 0.f, S1 = 0.f, Q1 = 0.f;
#pragma unroll
        for (int g2 = 0; g2 < 8; g2++) {
            S0 += red[g2][0][cl]; Q0 += red[g2][1][cl];
            S1 += red[g2][2][cl]; Q1 += red[g2][3][cl];
        }
        float mn0 = S0 * (1.f / Hc), v0 = Q0 * (1.f / Hc) - mn0 * mn0;
        float mn1 = S1 * (1.f / Hc), v1 = Q1 * (1.f / Hc) - mn1 * mn1;
        g_mean[b * Tn + 2 * nb]     = mn0;
        g_rstd[b * Tn + 2 * nb]     = rsqrtf(v0 + 1e-5f);
        g_mean[b * Tn + 2 * nb + 1] = mn1;
        g_rstd[b * Tn + 2 * nb + 1] = rsqrtf(v1 + 1e-5f);
    }
}

// ---------------- conv2 epilogue: transform + LN stats + LN2/relu/dot + durations --
__global__ __launch_bounds__(256)
void wos2_dot(const float* __restrict__ M, const float* __restrict__ bias,
              const float* __restrict__ g2, const float* __restrict__ be2,
              const float* __restrict__ Wl, const float* __restrict__ bl,
              float* __restrict__ durF)
{
    extern __shared__ float sm[];
    float* ysm   = sm;                         // [Hc][2][32]
    float* red   = sm + Hc * 2 * 32;           // [8][4][32]
    float* stats = red + 8 * 4 * 32;           // [4][32]
    float* dred  = stats + 4 * 32;             // [8][2][32]

    const int tid = threadIdx.x;
    const int cl = tid & 31;
    const int hgrp = tid >> 5;                 // 0..7
    const int col = blockIdx.x * 32 + cl;
    const int b = col >> 9, nb = col & 511;
    const float* mp = M + col;
    const size_t PH = (size_t)Hc * NTOT;

    float s0 = 0.f, q0 = 0.f, s1 = 0.f, q1 = 0.f;
    const int h0 = hgrp * 48;
#pragma unroll 4
    for (int ho = h0; ho < h0 + 48; ho++) {
        size_t off = (size_t)ho * NTOT;
        float m1 = __ldg(mp + off);
        float m2 = __ldg(mp + off + PH);
        float m3 = __ldg(mp + off + 2 * PH);
        float m4 = __ldg(mp + off + 3 * PH);
        float bi = __ldg(bias + ho);
        float y0 = m1 + m2 + m3 + bi;
        float y1 = m2 - m3 - m4 + bi;
        ysm[(ho * 2 + 0) * 32 + cl] = y0;
        ysm[(ho * 2 + 1) * 32 + cl] = y1;
        s0 += y0; q0 += y0 * y0;
        s1 += y1; q1 += y1 * y1;
    }
    red[(hgrp * 4 + 0) * 32 + cl] = s0;
    red[(hgrp * 4 + 1) * 32 + cl] = q0;
    red[(hgrp * 4 + 2) * 32 + cl] = s1;
    red[(hgrp * 4 + 3) * 32 + cl] = q1;
    __syncthreads();
    if (hgrp == 0) {
        float S0 = 0.f, Q0 = 0.f, S1 = 0.f, Q1 = 0.f;
#pragma unroll
        for (int g = 0; g < 8; g++) {
            S0 += red[(g * 4 + 0) * 32 + cl]; Q0 += red[(g * 4 + 1) * 32 + cl];
            S1 += red[(g * 4 + 2) * 32 + cl]; Q1 += red[(g * 4 + 3) * 32 + cl];
        }
        float mn0 = S0 * (1.f / Hc), v0 = Q0 * (1.f / Hc) - mn0 * mn0;
        float mn1 = S1 * (1.f / Hc), v1 = Q1 * (1.f / Hc) - mn1 * mn1;
        stats[0 * 32 + cl] = mn0;
        stats[1 * 32 + cl] = rsqrtf(v0 + 1e-5f);
        stats[2 * 32 + cl] = mn1;
        stats[3 * 32 + cl] = rsqrtf(v1 + 1e-5f);
    }
    __syncthreads();

    const float mn0 = stats[0 * 32 + cl], r0 = stats[1 * 32 + cl];
    const float mn1 = stats[2 * 32 + cl], r1 = stats[3 * 32 + cl];
    float d0 = 0.f, d1 = 0.f;
#pragma unroll 4
    for (int ho = h0; ho < h0 + 48; ho++) {
        float gv = __ldg(g2 + ho), bev = __ldg(be2 + ho), wv = __ldg(Wl + ho);
        float y0 = ysm[(ho * 2 + 0) * 32 + cl];
        float y1 = ysm[(ho * 2 + 1) * 32 + cl];
        d0 += fmaxf((y0 - mn0) * r0 * gv + bev, 0.f) * wv;
        d1 += fmaxf((y1 - mn1) * r1 * gv + bev, 0.f) * wv;
    }
    dred[(hgrp * 2 + 0) * 32 + cl] = d0;
    dred[(hgrp * 2 + 1) * 32 + cl] = d1;
    __syncthreads();
    if (hgrp == 0) {
        float D0 = 0.f, D1 = 0.f;
#pragma unroll
        for (int g = 0; g < 8; g++) {
            D0 += dred[(g * 2 + 0) * 32 + cl];
            D1 += dred[(g * 2 + 1) * 32 + cl];
        }
        float blv = __ldg(bl);
        float z0 = fmaxf(D0 + blv, 0.f);
        float z1 = fmaxf(D1 + blv, 0.f);
        int du0 = (int)floorf(expf(z0));
        int du1 = (int)floorf(expf(z1));
        g_dur[b * Tn + 2 * nb]     = du0;
        g_dur[b * Tn + 2 * nb + 1] = du1;
        durF[b * Tn + 2 * nb]      = (float)du0;
        durF[b * Tn + 2 * nb + 1]  = (float)du1;
    }
}

// ---------------- per-batch inclusive cumsum: warp-scan, 4 elems/thread ----------
__global__ void cumsum_k()
{
    const int b = blockIdx.x, tid = threadIdx.x;
    const int lane = tid & 31, wid = tid >> 5;
    int4 v = *(const int4*)&g_dur[b * Tn + tid * 4];
    int s0 = v.x, s1 = s0 + v.y, s2 = s1 + v.z, s3 = s2 + v.w;
    int tsum = s3;
#pragma unroll
    for (int off = 1; off < 32; off <<= 1) {
        int n = __shfl_up_sync(0xFFFFFFFFu, tsum, off);
        if (lane >= off) tsum += n;
    }
    __shared__ int wsum[8];
    if (lane == 31) wsum[wid] = tsum;
    __syncthreads();
    int wpre = 0;
#pragma unroll
    for (int i = 0; i < 8; i++) wpre += (i < wid) ? wsum[i] : 0;
    int epre = wpre + tsum - s3;        // exclusive prefix for this thread
    *(int4*)&g_cum[b * Tn + tid * 4] = make_int4(epre + s0, epre + s1,
                                                 epre + s2, epre + s3);
}

// ---------------- ragged gather: 4 pos/thread, float4 stores, h-split ------------
__global__ void gather_k(const float* __restrict__ X, float* __restrict__ outAligned)
{
    __shared__ int sc[Tn];
    const int b = blockIdx.y;
    const int tid = threadIdx.x;
#pragma unroll
    for (int e = 0; e < 4; e++) sc[tid + 256 * e] = g_cum[b * Tn + tid + 256 * e];
    __syncthreads();

    const int pos0 = (blockIdx.x * 256 + tid) * 4;   // gridDim.x = MAXL/1024 = 4
    const int total = sc[Tn - 1];
    int idx[4];
    bool val[4];
#pragma unroll
    for (int e = 0; e < 4; e++) {
        int pos = pos0 + e;
        val[e] = pos < total;
        int lo = 0, hi = Tn;
        while (lo < hi) {
            int mid = (lo + hi) >> 1;
            if (sc[mid] <= pos) lo = mid + 1; else hi = mid;
        }
        idx[e] = min(lo, Tn - 1);
    }

    const int h0 = blockIdx.z * 128;                 // 3 z-slices of 128 h
    const float* xb = X + (size_t)b * Hc * Tn;
    float* ob = outAligned + (size_t)b * Hc * MAXL + pos0;
#pragma unroll 2
    for (int h = h0; h < h0 + 128; h++) {
        const float* xr = xb + (size_t)h * Tn;
        float4 vv;
        vv.x = val[0] ? __ldg(xr + idx[0]) : 0.f;
        vv.y = val[1] ? __ldg(xr + idx[1]) : 0.f;
        vv.z = val[2] ? __ldg(xr + idx[2]) : 0.f;
        vv.w = val[3] ? __ldg(xr + idx[3]) : 0.f;
        *(float4*)(ob + (size_t)h * MAXL) = vv;
    }
}

// ---------------------------------------------------------------------------------
extern "C" void kernel_launch(void* const* d_in, const int* in_sizes, int n_in,
                              void* d_out, int out_size)
{
    const float* x  = (const float*)d_in[0];
    const float* W1 = (const float*)d_in[1];
    const float* b1 = (const float*)d_in[2];
    const float* g1 = (const float*)d_in[3];
    const float* be1= (const float*)d_in[4];
    const float* W2 = (const float*)d_in[5];
    const float* b2 = (const float*)d_in[6];
    const float* g2 = (const float*)d_in[7];
    const float* be2= (const float*)d_in[8];
    const float* Wl = (const float*)d_in[9];
    const float* bl = (const float*)d_in[10];

    float* out = (float*)d_out;
    float* outDur     = out;
    float* outAligned = out + Bq * Tn;

    float *buf1, *Mbuf, *Vf, *Bf;
    cudaGetSymbolAddress((void**)&buf1, g_buf1);
    cudaGetSymbolAddress((void**)&Mbuf, g_M);
    cudaGetSymbolAddress((void**)&Vf, g_Vf);
    cudaGetSymbolAddress((void**)&Bf, g_Bf);
    float* Bf1 = Bf;
    float* Bf2 = Bf + 4 * 2 * KT * NT * 64;

    const int WOS2_SMEM = (Hc * 2 * 32 + 8 * 4 * 32 + 4 * 32 + 8 * 2 * 32) * 4;
    cudaFuncSetAttribute(wos2_dot, cudaFuncAttributeMaxDynamicSharedMemorySize,
                         WOS2_SMEM);

    dim3 mma_grid(NTOT / 128, Hc / 64, 4);   // (128, 6, 4)

    bprep2<<<dim3((KT * NT) / 8, 2), 256>>>(W1, W2, Bf);

    // conv1
    vprep<<<(KT * MT) / 8, 256>>>(x, Vf, 0, g1, be1);
    wino_mma<<<mma_grid, 256>>>(Vf, Bf1, Mbuf);
    wino_out_stats<<<NTOT / 32, 256>>>(Mbuf, b1, buf1);
    // conv2 (LN1 + relu fused into vprep); epilogue fused through durations
    vprep<<<(KT * MT) / 8, 256>>>(buf1, Vf, 1, g1, be1);
    wino_mma<<<mma_grid, 256>>>(Vf, Bf2, Mbuf);
    wos2_dot<<<NTOT / 32, 256, WOS2_SMEM>>>(Mbuf, b2, g2, be2, Wl, bl, outDur);

    cumsum_k<<<Bq, 256>>>();
    gather_k<<<dim3(MAXL / 1024, Bq, 3), 256>>>(x, outAligned);
}

// round 15
// speedup vs baseline: 1.0796x; 1.0796x over previous
#include <cuda_runtime.h>
#include <math.h>
#include <stdint.h>

#define Bq   32
#define Hc   384
#define Tn   1024
#define MAXL 4096
#define NBLK 512               // T/2 winograd blocks per batch
#define NTOT (Bq * NBLK)       // 16384 GEMM columns (m-dim)
#define KT   48                // 384/8 k-chunks
#define MT   (NTOT / 16)       // 1024 m-tiles
#define NT   48                // 384/8 n-tiles (ho)

#define MMA_STAGE_BYTES 32768          // 8 warps * 4KB
#define MMA_SMEM (3 * MMA_STAGE_BYTES) // 96KB

// ---------------- scratch ----------------
__device__ float g_buf1[(size_t)Bq * Hc * Tn];
__device__ float g_M[4][Hc][NTOT];                       // phase GEMM outputs
__device__ float g_Vf[(size_t)4 * 2 * KT * MT * 128];    // A frags [p][h][kt][mt][lane][4]
__device__ float g_Bf[2][4 * 2 * KT * NT * 64];          // B frags [conv][p][h][kt][nt][lane][2]
__device__ float g_mean[Bq * Tn];
__device__ float g_rstd[Bq * Tn];
__device__ int   g_dur[Bq * Tn];
__device__ int   g_cum[Bq * Tn];

__device__ __forceinline__ uint32_t f2tf32(float x)
{
    uint32_t r;
    asm("cvt.rna.tf32.f32 %0, %1;" : "=r"(r) : "f"(x));
    return r;
}
__device__ __forceinline__ void tf32_split(float x, float& h, float& l)
{
    uint32_t hb = f2tf32(x);
    h = __uint_as_float(hb);
    l = __uint_as_float(f2tf32(x - h));
}
__device__ __forceinline__ uint32_t smem_u32(const void* p)
{
    uint32_t a;
    asm("{ .reg .u64 t; cvta.to.shared.u64 t, %1; cvt.u32.u64 %0, t; }" : "=r"(a) : "l"(p));
    return a;
}

#define MMA_TF32(c, a, b) \
    asm volatile("mma.sync.aligned.m16n8k8.row.col.f32.tf32.tf32.f32 " \
        "{%0,%1,%2,%3}, {%4,%5,%6,%7}, {%8,%9}, {%0,%1,%2,%3};" \
        : "+f"((c)[0]), "+f"((c)[1]), "+f"((c)[2]), "+f"((c)[3]) \
        : "r"(__float_as_uint((a).x)), "r"(__float_as_uint((a).y)), \
          "r"(__float_as_uint((a).z)), "r"(__float_as_uint((a).w)), \
          "r"(__float_as_uint((b).x)), "r"(__float_as_uint((b).y)))

#define CP16(s, g) asm volatile("cp.async.ca.shared.global [%0], [%1], 16;" :: "r"(s), "l"(g))
#define CP8(s, g)  asm volatile("cp.async.ca.shared.global [%0], [%1], 8;"  :: "r"(s), "l"(g))
#define CP_COMMIT() asm volatile("cp.async.commit_group;" ::: "memory")
#define CP_WAIT(n)  asm volatile("cp.async.wait_group %0;" :: "n"(n) : "memory")

// ---------------- V prep: X -> A fragments (split hi/lo); optional fused LN+relu --
__global__ void vprep(const float* __restrict__ X, float* __restrict__ Af,
                      int useLN, const float* __restrict__ gam,
                      const float* __restrict__ bet)
{
    int gw = blockIdx.x * 8 + (threadIdx.x >> 5);   // warp per (kt, mt)
    int lane = threadIdx.x & 31;
    int kt = gw >> 10;
    int mt = gw & 1023;
    int g = lane >> 2, t4 = lane & 3;

    float4 outv[4][2];
#pragma unroll
    for (int s = 0; s < 4; s++) {
        int r  = g + ((s & 1) ? 8 : 0);
        int kk = t4 + ((s & 2) ? 4 : 0);
        int m = mt * 16 + r;
        int b = m >> 9, nb = m & 511;
        int hi = kt * 8 + kk;
        const float* xp = X + ((size_t)b * Hc + hi) * Tn;
        int t2 = 2 * nb;
        float gv = 1.f, bv = 0.f;
        float mn1 = 0.f, rs1 = 1.f, mn2 = 0.f, rs2 = 1.f;
        if (useLN) {
            gv = __ldg(gam + hi); bv = __ldg(bet + hi);
            mn1 = g_mean[b * Tn + t2];     rs1 = g_rstd[b * Tn + t2];
            mn2 = g_mean[b * Tn + t2 + 1]; rs2 = g_rstd[b * Tn + t2 + 1];
        }
        float2 dc = *(const float2*)(xp + t2);
        float d1 = dc.x, d2 = dc.y;
        float d0 = (t2 > 0) ? __ldg(xp + t2 - 1) : 0.f;
        float d3 = (t2 + 2 < Tn) ? __ldg(xp + t2 + 2) : 0.f;
        if (useLN) {
            d1 = fmaxf((d1 - mn1) * rs1 * gv + bv, 0.f);
            d2 = fmaxf((d2 - mn2) * rs2 * gv + bv, 0.f);
            if (t2 > 0)
                d0 = fmaxf((d0 - g_mean[b * Tn + t2 - 1]) * g_rstd[b * Tn + t2 - 1] * gv + bv, 0.f);
            if (t2 + 2 < Tn)
                d3 = fmaxf((d3 - g_mean[b * Tn + t2 + 2]) * g_rstd[b * Tn + t2 + 2] * gv + bv, 0.f);
        }
        float v[4] = {d0 - d2, d1 + d2, d2 - d1, d1 - d3};
#pragma unroll
        for (int p = 0; p < 4; p++) {
            float h, l;
            tf32_split(v[p], h, l);
            ((float*)&outv[p][0])[s] = h;
            ((float*)&outv[p][1])[s] = l;
        }
    }
#pragma unroll
    for (int p = 0; p < 4; p++)
#pragma unroll
        for (int h = 0; h < 2; h++)
            *(float4*)(Af + ((((size_t)(p * 2 + h) * KT + kt) * MT + mt) * 128) + lane * 4)
                = outv[p][h];
}

// ---------------- B prep (both convs in one launch): W -> U_p fragments -----------
__global__ void bprep2(const float* __restrict__ W1, const float* __restrict__ W2,
                       float* __restrict__ BfAll)
{
    int conv = blockIdx.y;
    const float* W = conv ? W2 : W1;
    float* Bf = BfAll + (size_t)conv * 4 * 2 * KT * NT * 64;

    int gw = blockIdx.x * 8 + (threadIdx.x >> 5);
    int lane = threadIdx.x & 31;
    int kt = gw / NT, nt = gw % NT;
    int g = lane >> 2, t4 = lane & 3;
    int ho = nt * 8 + g;

    float2 outv[4][2];
#pragma unroll
    for (int s = 0; s < 2; s++) {
        int hi = kt * 8 + t4 + s * 4;
        const float* wp = W + ((size_t)ho * Hc + hi) * 3;
        float g0 = __ldg(wp), g1 = __ldg(wp + 1), g2 = __ldg(wp + 2);
        float u[4] = {g0, 0.5f * (g0 + g1 + g2), 0.5f * (g0 - g1 + g2), g2};
#pragma unroll
        for (int p = 0; p < 4; p++) {
            float h, l;
            tf32_split(u[p], h, l);
            ((float*)&outv[p][0])[s] = h;
            ((float*)&outv[p][1])[s] = l;
        }
    }
#pragma unroll
    for (int p = 0; p < 4; p++)
#pragma unroll
        for (int h = 0; h < 2; h++)
            *(float2*)(Bf + ((((size_t)(p * 2 + h) * KT + kt) * NT + nt) * 64) + lane * 2)
                = outv[p][h];
}

// ---------------- phase GEMM: cp.async 3-stage pipeline, thread-local slots -------
// Each thread cp.asyncs exactly the fragment bytes IT will lds (no cross-thread
// sharing -> wait_group alone orders; no __syncthreads in the pipeline).
__global__ __launch_bounds__(256, 2)
void wino_mma(const float* __restrict__ Af, const float* __restrict__ Bf,
              float* __restrict__ M)
{
    extern __shared__ char sm[];
    const uint32_t smb = smem_u32(sm);
    const int p = blockIdx.z, mc = blockIdx.x, nc = blockIdx.y;
    const int w = threadIdx.x >> 5, lane = threadIdx.x & 31;
    const int wm = w & 3, wn = w >> 2;
    const int mt0 = mc * 8 + wm * 2;
    const int nt0 = nc * 8 + wn * 4;

    float c[8][4];
#pragma unroll
    for (int i = 0; i < 8; i++)
#pragma unroll
        for (int r = 0; r < 4; r++) c[i][r] = 0.f;

    const float* A0 = Af + (size_t)(p * 2 + 0) * KT * MT * 128 + (size_t)mt0 * 128 + lane * 4;
    const float* A1 = Af + (size_t)(p * 2 + 1) * KT * MT * 128 + (size_t)mt0 * 128 + lane * 4;
    const float* B0 = Bf + (size_t)(p * 2 + 0) * KT * NT * 64 + (size_t)nt0 * 64 + lane * 2;
    const float* B1 = Bf + (size_t)(p * 2 + 1) * KT * NT * 64 + (size_t)nt0 * 64 + lane * 2;

    const uint32_t wbase = smb + w * 4096;

    auto produce = [&](int kt) {
        uint32_t sb = wbase + (kt % 3) * MMA_STAGE_BYTES;
        const size_t ao = (size_t)kt * MT * 128;
        const size_t bo = (size_t)kt * NT * 64;
        CP16(sb + (uint32_t)((0 * 32 + lane) * 16), A0 + ao);         // i=0 hi
        CP16(sb + (uint32_t)((1 * 32 + lane) * 16), A1 + ao);         // i=0 lo
        CP16(sb + (uint32_t)((2 * 32 + lane) * 16), A0 + ao + 128);   // i=1 hi
        CP16(sb + (uint32_t)((3 * 32 + lane) * 16), A1 + ao + 128);   // i=1 lo
        uint32_t bb = sb + 2048;
#pragma unroll
        for (int j = 0; j < 4; j++) {
            CP8(bb + (uint32_t)(((j * 2 + 0) * 32 + lane) * 8), B0 + bo + (size_t)j * 64);
            CP8(bb + (uint32_t)(((j * 2 + 1) * 32 + lane) * 8), B1 + bo + (size_t)j * 64);
        }
        CP_COMMIT();
    };

    produce(0);
    produce(1);
#pragma unroll 3
    for (int kt = 0; kt < KT; kt++) {
        if (kt + 2 < KT) { produce(kt + 2); CP_WAIT(2); }
        else             { CP_WAIT(0); }
        const char* sb = sm + (size_t)(w * 4096) + (size_t)(kt % 3) * MMA_STAGE_BYTES;
        float4 a[2][2];
        float2 b[4][2];
#pragma unroll
        for (int i = 0; i < 2; i++) {
            a[i][0] = *(const float4*)(sb + ((i * 2 + 0) * 32 + lane) * 16);
            a[i][1] = *(const float4*)(sb + ((i * 2 + 1) * 32 + lane) * 16);
        }
        const char* bbp = sb + 2048;
#pragma unroll
        for (int j = 0; j < 4; j++) {
            b[j][0] = *(const float2*)(bbp + ((j * 2 + 0) * 32 + lane) * 8);
            b[j][1] = *(const float2*)(bbp + ((j * 2 + 1) * 32 + lane) * 8);
        }
#pragma unroll
        for (int i = 0; i < 2; i++)
#pragma unroll
            for (int j = 0; j < 4; j++) {
                MMA_TF32(c[i * 4 + j], a[i][0], b[j][0]);
                MMA_TF32(c[i * 4 + j], a[i][0], b[j][1]);
                MMA_TF32(c[i * 4 + j], a[i][1], b[j][0]);
            }
    }

    const int g = lane >> 2, t4 = lane & 3;
#pragma unroll
    for (int i = 0; i < 2; i++)
#pragma unroll
        for (int j = 0; j < 4; j++) {
            int m  = mc * 128 + wm * 32 + i * 16 + g;
            int ho = nc * 64 + wn * 32 + j * 8 + 2 * t4;
            float* mp = M + ((size_t)p * Hc + ho) * NTOT + m;
            mp[0]        = c[i * 4 + j][0];
            mp[NTOT]     = c[i * 4 + j][1];
            mp[8]        = c[i * 4 + j][2];
            mp[NTOT + 8] = c[i * 4 + j][3];
        }
}

// ---------------- conv1 epilogue: output transform + LN stats ----------
__global__ __launch_bounds__(256, 4)
void wino_out_stats(const float* __restrict__ M, const float* __restrict__ bias,
                    float* __restrict__ Y)
{
    __shared__ float red[8][4][32];
    const int tid = threadIdx.x;
    const int cl = tid & 31;
    const int hgrp = tid >> 5;                 // 0..7
    const int col = blockIdx.x * 32 + cl;      // 0..16383
    const int b = col >> 9, nb = col & 511;
    const float* mp = M + col;
    const size_t PH = (size_t)Hc * NTOT;
    float* yb = Y + (size_t)b * Hc * Tn + 2 * nb;

    float s0 = 0.f, q0 = 0.f, s1 = 0.f, q1 = 0.f;
    const int h0 = hgrp * 48;
#pragma unroll 4
    for (int ho = h0; ho < h0 + 48; ho++) {
        size_t off = (size_t)ho * NTOT;
        float m1 = __ldg(mp + off);
        float m2 = __ldg(mp + off + PH);
        float m3 = __ldg(mp + off + 2 * PH);
        float m4 = __ldg(mp + off + 3 * PH);
        float bi = __ldg(bias + ho);
        float y0 = m1 + m2 + m3 + bi;
        float y1 = m2 - m3 - m4 + bi;
        *(float2*)(yb + (size_t)ho * Tn) = make_float2(y0, y1);
        s0 += y0; q0 += y0 * y0;
        s1 += y1; q1 += y1 * y1;
    }
    red[hgrp][0][cl] = s0;
    red[hgrp][1][cl] = q0;
    red[hgrp][2][cl] = s1;
    red[hgrp][3][cl] = q1;
    __syncthreads();
    if (hgrp == 0) {
        float S0 = 0.f, Q0 = 0.f, S1 = 0.f, Q1 = 0.f;
#pragma unroll
        for (int g2 = 0; g2 < 8; g2++) {
            S0 += red[g2][0][cl]; Q0 += red[g2][1][cl];
            S1 += red[g2][2][cl]; Q1 += red[g2][3][cl];
        }
        float mn0 = S0 * (1.f / Hc), v0 = Q0 * (1.f / Hc) - mn0 * mn0;
        float mn1 = S1 * (1.f / Hc), v1 = Q1 * (1.f / Hc) - mn1 * mn1;
        g_mean[b * Tn + 2 * nb]     = mn0;
        g_rstd[b * Tn + 2 * nb]     = rsqrtf(v0 + 1e-5f);
        g_mean[b * Tn + 2 * nb + 1] = mn1;
        g_rstd[b * Tn + 2 * nb + 1] = rsqrtf(v1 + 1e-5f);
    }
}

// ---------------- conv2 epilogue: transform + LN stats + LN2/relu/dot + durations --
__global__ __launch_bounds__(256)
void wos2_dot(const float* __restrict__ M, const float* __restrict__ bias,
              const float* __restrict__ g2, const float* __restrict__ be2,
              const float* __restrict__ Wl, const float* __restrict__ bl,
              float* __restrict__ durF)
{
    extern __shared__ float smf[];
    float* ysm   = smf;                        // [Hc][2][32]
    float* red   = smf + Hc * 2 * 32;          // [8][4][32]
    float* stats = red + 8 * 4 * 32;           // [4][32]
    float* dred  = stats + 4 * 32;             // [8][2][32]

    const int tid = threadIdx.x;
    const int cl = tid & 31;
    const int hgrp = tid >> 5;                 // 0..7
    const int col = blockIdx.x * 32 + cl;
    const int b = col >> 9, nb = col & 511;
    const float* mp = M + col;
    const size_t PH = (size_t)Hc * NTOT;

    float s0 = 0.f, q0 = 0.f, s1 = 0.f, q1 = 0.f;
    const int h0 = hgrp * 48;
#pragma unroll 4
    for (int ho = h0; ho < h0 + 48; ho++) {
        size_t off = (size_t)ho * NTOT;
        float m1 = __ldg(mp + off);
        float m2 = __ldg(mp + off + PH);
        float m3 = __ldg(mp + off + 2 * PH);
        float m4 = __ldg(mp + off + 3 * PH);
        float bi = __ldg(bias + ho);
        float y0 = m1 + m2 + m3 + bi;
        float y1 = m2 - m3 - m4 + bi;
        ysm[(ho * 2 + 0) * 32 + cl] = y0;
        ysm[(ho * 2 + 1) * 32 + cl] = y1;
        s0 += y0; q0 += y0 * y0;
        s1 += y1; q1 += y1 * y1;
    }
    red[(hgrp * 4 + 0) * 32 + cl] = s0;
    red[(hgrp * 4 + 1) * 32 + cl] = q0;
    red[(hgrp * 4 + 2) * 32 + cl] = s1;
    red[(hgrp * 4 + 3) * 32 + cl] = q1;
    __syncthreads();
    if (hgrp == 0) {
        float S0 = 0.f, Q0 = 0.f, S1 = 0.f, Q1 = 0.f;
#pragma unroll
        for (int g = 0; g < 8; g++) {
            S0 += red[(g * 4 + 0) * 32 + cl]; Q0 += red[(g * 4 + 1) * 32 + cl];
            S1 += red[(g * 4 + 2) * 32 + cl]; Q1 += red[(g * 4 + 3) * 32 + cl];
        }
        float mn0 = S0 * (1.f / Hc), v0 = Q0 * (1.f / Hc) - mn0 * mn0;
        float mn1 = S1 * (1.f / Hc), v1 = Q1 * (1.f / Hc) - mn1 * mn1;
        stats[0 * 32 + cl] = mn0;
        stats[1 * 32 + cl] = rsqrtf(v0 + 1e-5f);
        stats[2 * 32 + cl] = mn1;
        stats[3 * 32 + cl] = rsqrtf(v1 + 1e-5f);
    }
    __syncthreads();

    const float mn0 = stats[0 * 32 + cl], r0 = stats[1 * 32 + cl];
    const float mn1 = stats[2 * 32 + cl], r1 = stats[3 * 32 + cl];
    float d0 = 0.f, d1 = 0.f;
#pragma unroll 4
    for (int ho = h0; ho < h0 + 48; ho++) {
        float gv = __ldg(g2 + ho), bev = __ldg(be2 + ho), wv = __ldg(Wl + ho);
        float y0 = ysm[(ho * 2 + 0) * 32 + cl];
        float y1 = ysm[(ho * 2 + 1) * 32 + cl];
        d0 += fmaxf((y0 - mn0) * r0 * gv + bev, 0.f) * wv;
        d1 += fmaxf((y1 - mn1) * r1 * gv + bev, 0.f) * wv;
    }
    dred[(hgrp * 2 + 0) * 32 + cl] = d0;
    dred[(hgrp * 2 + 1) * 32 + cl] = d1;
    __syncthreads();
    if (hgrp == 0) {
        float D0 = 0.f, D1 = 0.f;
#pragma unroll
        for (int g = 0; g < 8; g++) {
            D0 += dred[(g * 2 + 0) * 32 + cl];
            D1 += dred[(g * 2 + 1) * 32 + cl];
        }
        float blv = __ldg(bl);
        float z0 = fmaxf(D0 + blv, 0.f);
        float z1 = fmaxf(D1 + blv, 0.f);
        int du0 = (int)floorf(expf(z0));
        int du1 = (int)floorf(expf(z1));
        g_dur[b * Tn + 2 * nb]     = du0;
        g_dur[b * Tn + 2 * nb + 1] = du1;
        durF[b * Tn + 2 * nb]      = (float)du0;
        durF[b * Tn + 2 * nb + 1]  = (float)du1;
    }
}

// ---------------- per-batch inclusive cumsum: warp-scan, 4 elems/thread ----------
__global__ void cumsum_k()
{
    const int b = blockIdx.x, tid = threadIdx.x;
    const int lane = tid & 31, wid = tid >> 5;
    int4 v = *(const int4*)&g_dur[b * Tn + tid * 4];
    int s0 = v.x, s1 = s0 + v.y, s2 = s1 + v.z, s3 = s2 + v.w;
    int tsum = s3;
#pragma unroll
    for (int off = 1; off < 32; off <<= 1) {
        int n = __shfl_up_sync(0xFFFFFFFFu, tsum, off);
        if (lane >= off) tsum += n;
    }
    __shared__ int wsum[8];
    if (lane == 31) wsum[wid] = tsum;
    __syncthreads();
    int wpre = 0;
#pragma unroll
    for (int i = 0; i < 8; i++) wpre += (i < wid) ? wsum[i] : 0;
    int epre = wpre + tsum - s3;        // exclusive prefix for this thread
    *(int4*)&g_cum[b * Tn + tid * 4] = make_int4(epre + s0, epre + s1,
                                                 epre + s2, epre + s3);
}

// ---------------- ragged gather: 4 pos/thread, float4 stores, h-split ------------
__global__ void gather_k(const float* __restrict__ X, float* __restrict__ outAligned)
{
    __shared__ int sc[Tn];
    const int b = blockIdx.y;
    const int tid = threadIdx.x;
#pragma unroll
    for (int e = 0; e < 4; e++) sc[tid + 256 * e] = g_cum[b * Tn + tid + 256 * e];
    __syncthreads();

    const int pos0 = (blockIdx.x * 256 + tid) * 4;   // gridDim.x = MAXL/1024 = 4
    const int total = sc[Tn - 1];
    int idx[4];
    bool val[4];
#pragma unroll
    for (int e = 0; e < 4; e++) {
        int pos = pos0 + e;
        val[e] = pos < total;
        int lo = 0, hi = Tn;
        while (lo < hi) {
            int mid = (lo + hi) >> 1;
            if (sc[mid] <= pos) lo = mid + 1; else hi = mid;
        }
        idx[e] = min(lo, Tn - 1);
    }

    const int h0 = blockIdx.z * 128;                 // 3 z-slices of 128 h
    const float* xb = X + (size_t)b * Hc * Tn;
    float* ob = outAligned + (size_t)b * Hc * MAXL + pos0;
#pragma unroll 2
    for (int h = h0; h < h0 + 128; h++) {
        const float* xr = xb + (size_t)h * Tn;
        float4 vv;
        vv.x = val[0] ? __ldg(xr + idx[0]) : 0.f;
        vv.y = val[1] ? __ldg(xr + idx[1]) : 0.f;
        vv.z = val[2] ? __ldg(xr + idx[2]) : 0.f;
        vv.w = val[3] ? __ldg(xr + idx[3]) : 0.f;
        *(float4*)(ob + (size_t)h * MAXL) = vv;
    }
}

// ---------------------------------------------------------------------------------
extern "C" void kernel_launch(void* const* d_in, const int* in_sizes, int n_in,
                              void* d_out, int out_size)
{
    const float* x  = (const float*)d_in[0];
    const float* W1 = (const float*)d_in[1];
    const float* b1 = (const float*)d_in[2];
    const float* g1 = (const float*)d_in[3];
    const float* be1= (const float*)d_in[4];
    const float* W2 = (const float*)d_in[5];
    const float* b2 = (const float*)d_in[6];
    const float* g2 = (const float*)d_in[7];
    const float* be2= (const float*)d_in[8];
    const float* Wl = (const float*)d_in[9];
    const float* bl = (const float*)d_in[10];

    float* out = (float*)d_out;
    float* outDur     = out;
    float* outAligned = out + Bq * Tn;

    float *buf1, *Mbuf, *Vf, *Bf;
    cudaGetSymbolAddress((void**)&buf1, g_buf1);
    cudaGetSymbolAddress((void**)&Mbuf, g_M);
    cudaGetSymbolAddress((void**)&Vf, g_Vf);
    cudaGetSymbolAddress((void**)&Bf, g_Bf);
    float* Bf1 = Bf;
    float* Bf2 = Bf + 4 * 2 * KT * NT * 64;

    const int WOS2_SMEM = (Hc * 2 * 32 + 8 * 4 * 32 + 4 * 32 + 8 * 2 * 32) * 4;
    cudaFuncSetAttribute(wos2_dot, cudaFuncAttributeMaxDynamicSharedMemorySize,
                         WOS2_SMEM);
    cudaFuncSetAttribute(wino_mma, cudaFuncAttributeMaxDynamicSharedMemorySize,
                         MMA_SMEM);

    dim3 mma_grid(NTOT / 128, Hc / 64, 4);   // (128, 6, 4)

    bprep2<<<dim3((KT * NT) / 8, 2), 256>>>(W1, W2, Bf);

    // conv1
    vprep<<<(KT * MT) / 8, 256>>>(x, Vf, 0, g1, be1);
    wino_mma<<<mma_grid, 256, MMA_SMEM>>>(Vf, Bf1, Mbuf);
    wino_out_stats<<<NTOT / 32, 256>>>(Mbuf, b1, buf1);
    // conv2 (LN1 + relu fused into vprep); epilogue fused through durations
    vprep<<<(KT * MT) / 8, 256>>>(buf1, Vf, 1, g1, be1);
    wino_mma<<<mma_grid, 256, MMA_SMEM>>>(Vf, Bf2, Mbuf);
    wos2_dot<<<NTOT / 32, 256, WOS2_SMEM>>>(Mbuf, b2, g2, be2, Wl, bl, outDur);

    cumsum_k<<<Bq, 256>>>();
    gather_k<<<dim3(MAXL / 1024, Bq, 3), 256>>>(x, outAligned);
}

// round 16
// speedup vs baseline: 1.4534x; 1.3462x over previous
#include <cuda_runtime.h>
#include <math.h>
#include <stdint.h>

#define Bq   32
#define Hc   384
#define Tn   1024
#define MAXL 4096
#define NBLK 512               // T/2 winograd blocks per batch
#define NTOT (Bq * NBLK)       // 16384 GEMM columns (m-dim)
#define KT   48                // 384/8 k-chunks
#define MT   (NTOT / 16)       // 1024 m-tiles
#define NT   48                // 384/8 n-tiles (ho)

// ---------------- scratch ----------------
__device__ float g_buf1[(size_t)Bq * Hc * Tn];
__device__ float g_M[4][Hc][NTOT];                       // phase GEMM outputs
__device__ float g_Vf[(size_t)4 * 2 * KT * MT * 128];    // A frags [p][h][kt][mt][lane][4]
__device__ float g_Bf[2][4 * 2 * KT * NT * 64];          // B frags [conv][p][h][kt][nt][lane][2]
__device__ float g_mean[Bq * Tn];
__device__ float g_rstd[Bq * Tn];
__device__ int   g_dur[Bq * Tn];
__device__ int   g_cum[Bq * Tn];

__device__ __forceinline__ uint32_t f2tf32(float x)
{
    uint32_t r;
    asm("cvt.rna.tf32.f32 %0, %1;" : "=r"(r) : "f"(x));
    return r;
}
__device__ __forceinline__ void tf32_split(float x, float& h, float& l)
{
    uint32_t hb = f2tf32(x);
    h = __uint_as_float(hb);
    l = __uint_as_float(f2tf32(x - h));
}

#define MMA_TF32(c, a, b) \
    asm volatile("mma.sync.aligned.m16n8k8.row.col.f32.tf32.tf32.f32 " \
        "{%0,%1,%2,%3}, {%4,%5,%6,%7}, {%8,%9}, {%0,%1,%2,%3};" \
        : "+f"((c)[0]), "+f"((c)[1]), "+f"((c)[2]), "+f"((c)[3]) \
        : "r"(__float_as_uint((a).x)), "r"(__float_as_uint((a).y)), \
          "r"(__float_as_uint((a).z)), "r"(__float_as_uint((a).w)), \
          "r"(__float_as_uint((b).x)), "r"(__float_as_uint((b).y)))

// ---------------- V prep: X -> A fragments (split hi/lo); optional fused LN+relu --
__global__ void vprep(const float* __restrict__ X, float* __restrict__ Af,
                      int useLN, const float* __restrict__ gam,
                      const float* __restrict__ bet)
{
    int gw = blockIdx.x * 8 + (threadIdx.x >> 5);   // warp per (kt, mt)
    int lane = threadIdx.x & 31;
    int kt = gw >> 10;
    int mt = gw & 1023;
    int g = lane >> 2, t4 = lane & 3;

    float4 outv[4][2];
#pragma unroll
    for (int s = 0; s < 4; s++) {
        int r  = g + ((s & 1) ? 8 : 0);
        int kk = t4 + ((s & 2) ? 4 : 0);
        int m = mt * 16 + r;
        int b = m >> 9, nb = m & 511;
        int hi = kt * 8 + kk;
        const float* xp = X + ((size_t)b * Hc + hi) * Tn;
        int t2 = 2 * nb;
        float gv = 1.f, bv = 0.f;
        float mn1 = 0.f, rs1 = 1.f, mn2 = 0.f, rs2 = 1.f;
        if (useLN) {
            gv = __ldg(gam + hi); bv = __ldg(bet + hi);
            mn1 = g_mean[b * Tn + t2];     rs1 = g_rstd[b * Tn + t2];
            mn2 = g_mean[b * Tn + t2 + 1]; rs2 = g_rstd[b * Tn + t2 + 1];
        }
        // aligned float2 covers d1, d2; only p0/p3 need odd neighbors
        float2 dc = *(const float2*)(xp + t2);
        float d1 = dc.x, d2 = dc.y;
        float d0 = (t2 > 0) ? __ldg(xp + t2 - 1) : 0.f;
        float d3 = (t2 + 2 < Tn) ? __ldg(xp + t2 + 2) : 0.f;
        if (useLN) {
            d1 = fmaxf((d1 - mn1) * rs1 * gv + bv, 0.f);
            d2 = fmaxf((d2 - mn2) * rs2 * gv + bv, 0.f);
            if (t2 > 0)
                d0 = fmaxf((d0 - g_mean[b * Tn + t2 - 1]) * g_rstd[b * Tn + t2 - 1] * gv + bv, 0.f);
            if (t2 + 2 < Tn)
                d3 = fmaxf((d3 - g_mean[b * Tn + t2 + 2]) * g_rstd[b * Tn + t2 + 2] * gv + bv, 0.f);
        }
        float v[4] = {d0 - d2, d1 + d2, d2 - d1, d1 - d3};
#pragma unroll
        for (int p = 0; p < 4; p++) {
            float h, l;
            tf32_split(v[p], h, l);
            ((float*)&outv[p][0])[s] = h;
            ((float*)&outv[p][1])[s] = l;
        }
    }
#pragma unroll
    for (int p = 0; p < 4; p++)
#pragma unroll
        for (int h = 0; h < 2; h++)
            *(float4*)(Af + ((((size_t)(p * 2 + h) * KT + kt) * MT + mt) * 128) + lane * 4)
                = outv[p][h];
}

// ---------------- B prep (both convs in one launch): W -> U_p fragments -----------
__global__ void bprep2(const float* __restrict__ W1, const float* __restrict__ W2,
                       float* __restrict__ BfAll)
{
    int conv = blockIdx.y;
    const float* W = conv ? W2 : W1;
    float* Bf = BfAll + (size_t)conv * 4 * 2 * KT * NT * 64;

    int gw = blockIdx.x * 8 + (threadIdx.x >> 5);
    int lane = threadIdx.x & 31;
    int kt = gw / NT, nt = gw % NT;
    int g = lane >> 2, t4 = lane & 3;
    int ho = nt * 8 + g;

    float2 outv[4][2];
#pragma unroll
    for (int s = 0; s < 2; s++) {
        int hi = kt * 8 + t4 + s * 4;
        const float* wp = W + ((size_t)ho * Hc + hi) * 3;
        float g0 = __ldg(wp), g1 = __ldg(wp + 1), g2 = __ldg(wp + 2);
        float u[4] = {g0, 0.5f * (g0 + g1 + g2), 0.5f * (g0 - g1 + g2), g2};
#pragma unroll
        for (int p = 0; p < 4; p++) {
            float h, l;
            tf32_split(u[p], h, l);
            ((float*)&outv[p][0])[s] = h;
            ((float*)&outv[p][1])[s] = l;
        }
    }
#pragma unroll
    for (int p = 0; p < 4; p++)
#pragma unroll
        for (int h = 0; h < 2; h++)
            *(float2*)(Bf + ((((size_t)(p * 2 + h) * KT + kt) * NT + nt) * 64) + lane * 2)
                = outv[p][h];
}

// ---------------- phase GEMM: 32m x 32n warp tile, 2 CTAs/SM (R13 verified) -------
__global__ __launch_bounds__(256, 2)
void wino_mma(const float* __restrict__ Af, const float* __restrict__ Bf,
              float* __restrict__ M)
{
    const int p = blockIdx.z, mc = blockIdx.x, nc = blockIdx.y;
    const int w = threadIdx.x >> 5, lane = threadIdx.x & 31;
    const int wm = w & 3, wn = w >> 2;
    const int mt0 = mc * 8 + wm * 2;
    const int nt0 = nc * 8 + wn * 4;

    float c[8][4];
#pragma unroll
    for (int i = 0; i < 8; i++)
#pragma unroll
        for (int r = 0; r < 4; r++) c[i][r] = 0.f;

    const float* A0 = Af + (size_t)(p * 2 + 0) * KT * MT * 128 + (size_t)mt0 * 128 + lane * 4;
    const float* A1 = Af + (size_t)(p * 2 + 1) * KT * MT * 128 + (size_t)mt0 * 128 + lane * 4;
    const float* B0 = Bf + (size_t)(p * 2 + 0) * KT * NT * 64 + (size_t)nt0 * 64 + lane * 2;
    const float* B1 = Bf + (size_t)(p * 2 + 1) * KT * NT * 64 + (size_t)nt0 * 64 + lane * 2;

    float4 a[2][2][2];   // [buf][tile][half]
    float2 b[2][4][2];   // [buf][tile][half]

    auto loadf = [&](int kt, int bi) {
        const size_t ao = (size_t)kt * MT * 128;
        const size_t bo = (size_t)kt * NT * 64;
#pragma unroll
        for (int i = 0; i < 2; i++) {
            a[bi][i][0] = __ldg((const float4*)(A0 + ao + (size_t)i * 128));
            a[bi][i][1] = __ldg((const float4*)(A1 + ao + (size_t)i * 128));
        }
#pragma unroll
        for (int j = 0; j < 4; j++) {
            b[bi][j][0] = __ldg((const float2*)(B0 + bo + (size_t)j * 64));
            b[bi][j][1] = __ldg((const float2*)(B1 + bo + (size_t)j * 64));
        }
    };

    loadf(0, 0);
#pragma unroll 2
    for (int kt = 0; kt < KT; kt++) {
        const int cur = kt & 1;
        if (kt + 1 < KT) loadf(kt + 1, cur ^ 1);
#pragma unroll
        for (int i = 0; i < 2; i++)
#pragma unroll
            for (int j = 0; j < 4; j++) {
                MMA_TF32(c[i * 4 + j], a[cur][i][0], b[cur][j][0]);
                MMA_TF32(c[i * 4 + j], a[cur][i][0], b[cur][j][1]);
                MMA_TF32(c[i * 4 + j], a[cur][i][1], b[cur][j][0]);
            }
    }

    const int g = lane >> 2, t4 = lane & 3;
#pragma unroll
    for (int i = 0; i < 2; i++)
#pragma unroll
        for (int j = 0; j < 4; j++) {
            int m  = mc * 128 + wm * 32 + i * 16 + g;
            int ho = nc * 64 + wn * 32 + j * 8 + 2 * t4;
            float* mp = M + ((size_t)p * Hc + ho) * NTOT + m;
            mp[0]        = c[i * 4 + j][0];
            mp[NTOT]     = c[i * 4 + j][1];
            mp[8]        = c[i * 4 + j][2];
            mp[NTOT + 8] = c[i * 4 + j][3];
        }
}

// ---------------- conv1 epilogue: output transform + LN stats ----------
__global__ __launch_bounds__(256, 4)
void wino_out_stats(const float* __restrict__ M, const float* __restrict__ bias,
                    float* __restrict__ Y)
{
    __shared__ float red[8][4][32];
    const int tid = threadIdx.x;
    const int cl = tid & 31;
    const int hgrp = tid >> 5;                 // 0..7
    const int col = blockIdx.x * 32 + cl;      // 0..16383
    const int b = col >> 9, nb = col & 511;
    const float* mp = M + col;
    const size_t PH = (size_t)Hc * NTOT;
    float* yb = Y + (size_t)b * Hc * Tn + 2 * nb;

    float s0 = 0.f, q0 = 0.f, s1 = 0.f, q1 = 0.f;
    const int h0 = hgrp * 48;
#pragma unroll 4
    for (int ho = h0; ho < h0 + 48; ho++) {
        size_t off = (size_t)ho * NTOT;
        float m1 = __ldg(mp + off);
        float m2 = __ldg(mp + off + PH);
        float m3 = __ldg(mp + off + 2 * PH);
        float m4 = __ldg(mp + off + 3 * PH);
        float bi = __ldg(bias + ho);
        float y0 = m1 + m2 + m3 + bi;
        float y1 = m2 - m3 - m4 + bi;
        *(float2*)(yb + (size_t)ho * Tn) = make_float2(y0, y1);
        s0 += y0; q0 += y0 * y0;
        s1 += y1; q1 += y1 * y1;
    }
    red[hgrp][0][cl] = s0;
    red[hgrp][1][cl] = q0;
    red[hgrp][2][cl] = s1;
    red[hgrp][3][cl] = q1;
    __syncthreads();
    if (hgrp == 0) {
        float S0 = 0.f, Q0 = 0.f, S1 = 0.f, Q1 = 0.f;
#pragma unroll
        for (int g2 = 0; g2 < 8; g2++) {
            S0 += red[g2][0][cl]; Q0 += red[g2][1][cl];
            S1 += red[g2][2][cl]; Q1 += red[g2][3][cl];
        }
        float mn0 = S0 * (1.f / Hc), v0 = Q0 * (1.f / Hc) - mn0 * mn0;
        float mn1 = S1 * (1.f / Hc), v1 = Q1 * (1.f / Hc) - mn1 * mn1;
        g_mean[b * Tn + 2 * nb]     = mn0;
        g_rstd[b * Tn + 2 * nb]     = rsqrtf(v0 + 1e-5f);
        g_mean[b * Tn + 2 * nb + 1] = mn1;
        g_rstd[b * Tn + 2 * nb + 1] = rsqrtf(v1 + 1e-5f);
    }
}

// ---------------- conv2 epilogue: transform + LN stats + LN2/relu/dot + durations --
__global__ __launch_bounds__(256)
void wos2_dot(const float* __restrict__ M, const float* __restrict__ bias,
              const float* __restrict__ g2, const float* __restrict__ be2,
              const float* __restrict__ Wl, const float* __restrict__ bl,
              float* __restrict__ durF)
{
    extern __shared__ float sm[];
    float* ysm   = sm;                         // [Hc][2][32]
    float* red   = sm + Hc * 2 * 32;           // [8][4][32]
    float* stats = red + 8 * 4 * 32;           // [4][32]
    float* dred  = stats + 4 * 32;             // [8][2][32]

    const int tid = threadIdx.x;
    const int cl = tid & 31;
    const int hgrp = tid >> 5;                 // 0..7
    const int col = blockIdx.x * 32 + cl;
    const int b = col >> 9, nb = col & 511;
    const float* mp = M + col;
    const size_t PH = (size_t)Hc * NTOT;

    float s0 = 0.f, q0 = 0.f, s1 = 0.f, q1 = 0.f;
    const int h0 = hgrp * 48;
#pragma unroll 4
    for (int ho = h0; ho < h0 + 48; ho++) {
        size_t off = (size_t)ho * NTOT;
        float m1 = __ldg(mp + off);
        float m2 = __ldg(mp + off + PH);
        float m3 = __ldg(mp + off + 2 * PH);
        float m4 = __ldg(mp + off + 3 * PH);
        float bi = __ldg(bias + ho);
        float y0 = m1 + m2 + m3 + bi;
        float y1 = m2 - m3 - m4 + bi;
        ysm[(ho * 2 + 0) * 32 + cl] = y0;
        ysm[(ho * 2 + 1) * 32 + cl] = y1;
        s0 += y0; q0 += y0 * y0;
        s1 += y1; q1 += y1 * y1;
    }
    red[(hgrp * 4 + 0) * 32 + cl] = s0;
    red[(hgrp * 4 + 1) * 32 + cl] = q0;
    red[(hgrp * 4 + 2) * 32 + cl] = s1;
    red[(hgrp * 4 + 3) * 32 + cl] = q1;
    __syncthreads();
    if (hgrp == 0) {
        float S0 = 0.f, Q0 = 0.f, S1 = 0.f, Q1 = 0.f;
#pragma unroll
        for (int g = 0; g < 8; g++) {
            S0 += red[(g * 4 + 0) * 32 + cl]; Q0 += red[(g * 4 + 1) * 32 + cl];
            S1 += red[(g * 4 + 2) * 32 + cl]; Q1 += red[(g * 4 + 3) * 32 + cl];
        }
        float mn0 = S0 * (1.f / Hc), v0 = Q0 * (1.f / Hc) - mn0 * mn0;
        float mn1 = S1 * (1.f / Hc), v1 = Q1 * (1.f / Hc) - mn1 * mn1;
        stats[0 * 32 + cl] = mn0;
        stats[1 * 32 + cl] = rsqrtf(v0 + 1e-5f);
        stats[2 * 32 + cl] = mn1;
        stats[3 * 32 + cl] = rsqrtf(v1 + 1e-5f);
    }
    __syncthreads();

    const float mn0 = stats[0 * 32 + cl], r0 = stats[1 * 32 + cl];
    const float mn1 = stats[2 * 32 + cl], r1 = stats[3 * 32 + cl];
    float d0 = 0.f, d1 = 0.f;
#pragma unroll 4
    for (int ho = h0; ho < h0 + 48; ho++) {
        float gv = __ldg(g2 + ho), bev = __ldg(be2 + ho), wv = __ldg(Wl + ho);
        float y0 = ysm[(ho * 2 + 0) * 32 + cl];
        float y1 = ysm[(ho * 2 + 1) * 32 + cl];
        d0 += fmaxf((y0 - mn0) * r0 * gv + bev, 0.f) * wv;
        d1 += fmaxf((y1 - mn1) * r1 * gv + bev, 0.f) * wv;
    }
    dred[(hgrp * 2 + 0) * 32 + cl] = d0;
    dred[(hgrp * 2 + 1) * 32 + cl] = d1;
    __syncthreads();
    if (hgrp == 0) {
        float D0 = 0.f, D1 = 0.f;
#pragma unroll
        for (int g = 0; g < 8; g++) {
            D0 += dred[(g * 2 + 0) * 32 + cl];
            D1 += dred[(g * 2 + 1) * 32 + cl];
        }
        float blv = __ldg(bl);
        float z0 = fmaxf(D0 + blv, 0.f);
        float z1 = fmaxf(D1 + blv, 0.f);
        int du0 = (int)floorf(expf(z0));
        int du1 = (int)floorf(expf(z1));
        g_dur[b * Tn + 2 * nb]     = du0;
        g_dur[b * Tn + 2 * nb + 1] = du1;
        durF[b * Tn + 2 * nb]      = (float)du0;
        durF[b * Tn + 2 * nb + 1]  = (float)du1;
    }
}

// ---------------- per-batch inclusive cumsum: warp-scan, 4 elems/thread ----------
__global__ void cumsum_k()
{
    const int b = blockIdx.x, tid = threadIdx.x;
    const int lane = tid & 31, wid = tid >> 5;
    int4 v = *(const int4*)&g_dur[b * Tn + tid * 4];
    int s0 = v.x, s1 = s0 + v.y, s2 = s1 + v.z, s3 = s2 + v.w;
    int tsum = s3;
#pragma unroll
    for (int off = 1; off < 32; off <<= 1) {
        int n = __shfl_up_sync(0xFFFFFFFFu, tsum, off);
        if (lane >= off) tsum += n;
    }
    __shared__ int wsum[8];
    if (lane == 31) wsum[wid] = tsum;
    __syncthreads();
    int wpre = 0;
#pragma unroll
    for (int i = 0; i < 8; i++) wpre += (i < wid) ? wsum[i] : 0;
    int epre = wpre + tsum - s3;        // exclusive prefix for this thread
    *(int4*)&g_cum[b * Tn + tid * 4] = make_int4(epre + s0, epre + s1,
                                                 epre + s2, epre + s3);
}

// ---------------- ragged gather: 4 pos/thread, float4 stores, h-split ------------
__global__ void gather_k(const float* __restrict__ X, float* __restrict__ outAligned)
{
    __shared__ int sc[Tn];
    const int b = blockIdx.y;
    const int tid = threadIdx.x;
#pragma unroll
    for (int e = 0; e < 4; e++) sc[tid + 256 * e] = g_cum[b * Tn + tid + 256 * e];
    __syncthreads();

    const int pos0 = (blockIdx.x * 256 + tid) * 4;   // gridDim.x = MAXL/1024 = 4
    const int total = sc[Tn - 1];
    int idx[4];
    bool val[4];
#pragma unroll
    for (int e = 0; e < 4; e++) {
        int pos = pos0 + e;
        val[e] = pos < total;
        int lo = 0, hi = Tn;
        while (lo < hi) {
            int mid = (lo + hi) >> 1;
            if (sc[mid] <= pos) lo = mid + 1; else hi = mid;
        }
        idx[e] = min(lo, Tn - 1);
    }

    const int h0 = blockIdx.z * 128;                 // 3 z-slices of 128 h
    const float* xb = X + (size_t)b * Hc * Tn;
    float* ob = outAligned + (size_t)b * Hc * MAXL + pos0;
#pragma unroll 2
    for (int h = h0; h < h0 + 128; h++) {
        const float* xr = xb + (size_t)h * Tn;
        float4 vv;
        vv.x = val[0] ? __ldg(xr + idx[0]) : 0.f;
        vv.y = val[1] ? __ldg(xr + idx[1]) : 0.f;
        vv.z = val[2] ? __ldg(xr + idx[2]) : 0.f;
        vv.w = val[3] ? __ldg(xr + idx[3]) : 0.f;
        *(float4*)(ob + (size_t)h * MAXL) = vv;
    }
}

// ---------------------------------------------------------------------------------
extern "C" void kernel_launch(void* const* d_in, const int* in_sizes, int n_in,
                              void* d_out, int out_size)
{
    const float* x  = (const float*)d_in[0];
    const float* W1 = (const float*)d_in[1];
    const float* b1 = (const float*)d_in[2];
    const float* g1 = (const float*)d_in[3];
    const float* be1= (const float*)d_in[4];
    const float* W2 = (const float*)d_in[5];
    const float* b2 = (const float*)d_in[6];
    const float* g2 = (const float*)d_in[7];
    const float* be2= (const float*)d_in[8];
    const float* Wl = (const float*)d_in[9];
    const float* bl = (const float*)d_in[10];

    float* out = (float*)d_out;
    float* outDur     = out;
    float* outAligned = out + Bq * Tn;

    float *buf1, *Mbuf, *Vf, *Bf;
    cudaGetSymbolAddress((void**)&buf1, g_buf1);
    cudaGetSymbolAddress((void**)&Mbuf, g_M);
    cudaGetSymbolAddress((void**)&Vf, g_Vf);
    cudaGetSymbolAddress((void**)&Bf, g_Bf);
    float* Bf1 = Bf;
    float* Bf2 = Bf + 4 * 2 * KT * NT * 64;

    const int WOS2_SMEM = (Hc * 2 * 32 + 8 * 4 * 32 + 4 * 32 + 8 * 2 * 32) * 4;
    cudaFuncSetAttribute(wos2_dot, cudaFuncAttributeMaxDynamicSharedMemorySize,
                         WOS2_SMEM);

    dim3 mma_grid(NTOT / 128, Hc / 64, 4);   // (128, 6, 4)

    bprep2<<<dim3((KT * NT) / 8, 2), 256>>>(W1, W2, Bf);

    // conv1
    vprep<<<(KT * MT) / 8, 256>>>(x, Vf, 0, g1, be1);
    wino_mma<<<mma_grid, 256>>>(Vf, Bf1, Mbuf);
    wino_out_stats<<<NTOT / 32, 256>>>(Mbuf, b1, buf1);
    // conv2 (LN1 + relu fused into vprep); epilogue fused through durations
    vprep<<<(KT * MT) / 8, 256>>>(buf1, Vf, 1, g1, be1);
    wino_mma<<<mma_grid, 256>>>(Vf, Bf2, Mbuf);
    wos2_dot<<<NTOT / 32, 256, WOS2_SMEM>>>(Mbuf, b2, g2, be2, Wl, bl, outDur);

    cumsum_k<<<Bq, 256>>>();
    gather_k<<<dim3(MAXL / 1024, Bq, 3), 256>>>(x, outAligned);
}